// round 7
// baseline (speedup 1.0000x reference)
#include <cuda_runtime.h>
#include <cstdint>

#define SEQ   4096
#define BATCH 64
#define DIM   96
#define HID   128
#define NROWS (SEQ*BATCH)

using u64 = unsigned long long;

// ---------------- scratch (static device globals) ---------------------------
__device__ float g_zx0[(size_t)NROWS*1024 + 65536];  // [row=t*64+b][n], +1 step pad
__device__ float g_zx1[(size_t)NROWS*1024 + 65536];
__device__ float g_ys0[(size_t)NROWS*256];           // [t][b][2H]
__device__ float g_ys1[(size_t)NROWS*256];

// ---------------- helpers ----------------------------------------------------
__device__ __forceinline__ float sigm(float x)   { return 1.f/(1.f+__expf(-x)); }
__device__ __forceinline__ float tanh_s(float x) { float e=__expf(2.f*x); return 1.f-2.f/(e+1.f); }
__device__ __forceinline__ void ffma2(u64 &d, u64 a, u64 b) {
    asm volatile("fma.rn.f32x2 %0, %1, %2, %0;" : "+l"(d) : "l"(a), "l"(b));
}
__device__ __forceinline__ void lds2(u64 &a, u64 &b, uint32_t addr) {
    asm volatile("ld.shared.v2.u64 {%0,%1}, [%2];" : "=l"(a), "=l"(b) : "r"(addr));
}
__device__ __forceinline__ void unpk(float &lo, float &hi, u64 v) {
    asm volatile("mov.b64 {%0,%1}, %2;" : "=f"(lo), "=f"(hi) : "l"(v));
}
__device__ __forceinline__ uint32_t f2tf32(float x) {
    uint32_t r; asm("cvt.rna.tf32.f32 %0, %1;" : "=r"(r) : "f"(x)); return r;
}
__device__ __forceinline__ void mma_tf32(float4 &c,
    uint32_t a0, uint32_t a1, uint32_t a2, uint32_t a3,
    uint32_t b0, uint32_t b1)
{
    asm volatile("mma.sync.aligned.m16n8k8.row.col.f32.tf32.tf32.f32 "
        "{%0,%1,%2,%3}, {%4,%5,%6,%7}, {%8,%9}, {%0,%1,%2,%3};"
        : "+f"(c.x), "+f"(c.y), "+f"(c.z), "+f"(c.w)
        : "r"(a0), "r"(a1), "r"(a2), "r"(a3), "r"(b0), "r"(b1));
}

// ---------------- input-projection GEMM: round-5 proven version --------------
template<int K, int LAYER>
__global__ void __launch_bounds__(256) mma_gemm(
    const float* __restrict__ Aext,
    const float* __restrict__ Wf, const float* __restrict__ Wb,
    const float* __restrict__ bf, const float* __restrict__ bb)
{
    __shared__ uint32_t As[128][36];
    __shared__ uint32_t Ws[128][36];

    const float* A = (LAYER == 0) ? Aext : (const float*)g_ys0;
    float*       Z = LAYER ? g_zx1 : g_zx0;

    const int n0 = blockIdx.x * 128;
    const int m0 = blockIdx.y * 128;
    const float* W    = (n0 < 512) ? (Wf + (size_t)n0*K) : (Wb + (size_t)(n0-512)*K);
    const float* bias = (n0 < 512) ? (bf + n0) : (bb + (n0-512));

    const int tid  = threadIdx.x;
    const int wid  = tid >> 5, lane = tid & 31;
    const int wm   = wid & 3,  wn   = wid >> 2;
    const int g    = lane >> 2, t   = lane & 3;

    float4 acc[2][8];
#pragma unroll
    for (int mi = 0; mi < 2; mi++)
#pragma unroll
        for (int ni = 0; ni < 8; ni++) acc[mi][ni] = make_float4(0.f,0.f,0.f,0.f);

    for (int k0 = 0; k0 < K; k0 += 32) {
#pragma unroll
        for (int i = 0; i < 4; i++) {
            int q = tid + i*256;
            int r = q >> 3, kq = q & 7;
            float4 av = *(const float4*)(A + (size_t)(m0+r)*K + k0 + kq*4);
            uint4 ua = { f2tf32(av.x), f2tf32(av.y), f2tf32(av.z), f2tf32(av.w) };
            *(uint4*)&As[r][kq*4] = ua;
            float4 wv = *(const float4*)(W + (size_t)r*K + k0 + kq*4);
            uint4 uw = { f2tf32(wv.x), f2tf32(wv.y), f2tf32(wv.z), f2tf32(wv.w) };
            *(uint4*)&Ws[r][kq*4] = uw;
        }
        __syncthreads();
#pragma unroll
        for (int kb = 0; kb < 32; kb += 8) {
            uint32_t a[2][4];
#pragma unroll
            for (int mi = 0; mi < 2; mi++) {
                int R = wm*32 + mi*16;
                a[mi][0] = As[R + g    ][kb + t    ];
                a[mi][1] = As[R + g + 8][kb + t    ];
                a[mi][2] = As[R + g    ][kb + t + 4];
                a[mi][3] = As[R + g + 8][kb + t + 4];
            }
#pragma unroll
            for (int ni = 0; ni < 8; ni++) {
                int N8 = wn*64 + ni*8;
                uint32_t b0 = Ws[N8 + g][kb + t    ];
                uint32_t b1 = Ws[N8 + g][kb + t + 4];
                mma_tf32(acc[0][ni], a[0][0], a[0][1], a[0][2], a[0][3], b0, b1);
                mma_tf32(acc[1][ni], a[1][0], a[1][1], a[1][2], a[1][3], b0, b1);
            }
        }
        __syncthreads();
    }

#pragma unroll
    for (int ni = 0; ni < 8; ni++) {
        int ncl = wn*64 + ni*8 + 2*t;
        float2 bv = *(const float2*)(bias + ncl);
#pragma unroll
        for (int mi = 0; mi < 2; mi++) {
            float4 cf = acc[mi][ni];
            int r0 = m0 + wm*32 + mi*16 + g;
            float2 o0 = { cf.x + bv.x, cf.y + bv.y };
            float2 o1 = { cf.z + bv.x, cf.w + bv.y };
            *(float2*)(Z + (size_t)r0*1024 + n0 + ncl)     = o0;
            *(float2*)(Z + (size_t)(r0+8)*1024 + n0 + ncl) = o1;
        }
    }
}

// ---------------- recurrence: one CTA per (cell, batch) ----------------------
// 128 CTAs x 512 threads. Thread j owns Whh row j (gate=j>>7, unit=j&127).
// k in [0,96): weights in 48 reg pairs. k in [96,128): weights in smem, laid
// out as 16B/thread chunks -> 8 LDS.128 per step. h[128] smem broadcast.
// z staging transposed to [unit][gate] so epilogue reads one LDS.128.
// wsm: [8 g8][512 j][2], hs: [128], zs: [128][4]
#define RSMEM (65536 + 512 + 2048)

template<int LAYER>
__global__ void __launch_bounds__(512, 1) recur_kernel(
    const float* __restrict__ whhf, const float* __restrict__ whhb)
{
    extern __shared__ char smraw[];
    u64*   wsm = (u64*)smraw;                       // [8][512][2]
    float* hs  = (float*)(smraw + 65536);           // [128]
    float* zs  = (float*)(smraw + 65536 + 512);     // [128][4] = [unit][gate]

    const int tid  = threadIdx.x;                   // = j (Whh row)
    const int cell = blockIdx.x >> 6;
    const int b    = blockIdx.x & 63;
    const float* whh = cell ? whhb : whhf;
    const float* zx  = LAYER ? g_zx1 : g_zx0;
    float*       ys  = LAYER ? g_ys1 : g_ys0;

    const int gate = tid >> 7;
    const int unit = tid & 127;

    const u64* wrow = (const u64*)whh + (size_t)tid*64;
    u64 wreg[48];
#pragma unroll
    for (int q = 0; q < 48; q++) wreg[q] = __ldg(wrow + q);
#pragma unroll
    for (int g8 = 0; g8 < 8; g8++) {
        wsm[(g8*512 + tid)*2 + 0] = __ldg(wrow + 48 + 2*g8);
        wsm[(g8*512 + tid)*2 + 1] = __ldg(wrow + 48 + 2*g8 + 1);
    }

    if (tid < 128) hs[tid] = 0.f;

    uint32_t hs_s  = (uint32_t)__cvta_generic_to_shared(hs);
    uint32_t wsm_s = (uint32_t)__cvta_generic_to_shared(wsm);
    uint32_t zs_s  = (uint32_t)__cvta_generic_to_shared(zs);

    const float* zptr = zx + (size_t)b*1024 + cell*512 + tid;
    float* ysp = ys + (size_t)b*256 + cell*128 + tid;
    float zcur = __ldcs(zptr);
    float c = 0.f;

    __syncthreads();

    for (int t = 0; t < SEQ; t++) {
        float znext = __ldcs(zptr + (size_t)(t+1)*65536);

        u64 a0 = 0ull, a1 = 0ull, a2 = 0ull, a3 = 0ull;
        // k in [96,128): h + w both via LDS.128
#pragma unroll
        for (int g8 = 0; g8 < 8; g8++) {
            u64 ha, hb, wa, wb;
            lds2(ha, hb, hs_s + 384 + g8*16);
            lds2(wa, wb, wsm_s + (g8*512 + tid)*16);
            ffma2(a0, wa, ha);
            ffma2(a1, wb, hb);
        }
        // k in [0,96): weights in regs
#pragma unroll
        for (int q = 0; q < 48; q += 2) {
            u64 ha, hb;
            lds2(ha, hb, hs_s + q*8);
            ffma2(a2, wreg[q],   ha);
            ffma2(a3, wreg[q+1], hb);
        }
        float x0,x1,x2,x3,y0,y1;
        unpk(x0,x1,a0); unpk(x2,x3,a1);
        unpk(y0,y1,a2);
        float s01 = (x0+x1) + (y0+y1);
        unpk(x0,x1,a3);
        zs[unit*4 + gate] = s01 + ((x2+x3) + (x0+x1)) + zcur;
        zcur = znext;
        __syncthreads();

        if (tid < 128) {
            float4 zq = *(float4*)&zs[tid*4];       // i,f,g,o for unit=tid
            float ig = sigm(zq.x), fg = sigm(zq.y), gg = tanh_s(zq.z), og = sigm(zq.w);
            c = fg*c + ig*gg;
            float h = og * tanh_s(c);
            hs[tid] = h;
            ysp[(size_t)t*16384] = h;
        }
        __syncthreads();
    }
}

// ---------------- final FC + sigmoid ----------------------------------------
__global__ void __launch_bounds__(256) fc_kernel(
    const float* __restrict__ fcw, const float* __restrict__ fcb,
    float* __restrict__ out)
{
    int gtid = blockIdx.x*blockDim.x + threadIdx.x;
    int row = gtid >> 5, lane = gtid & 31;
    if (row >= NROWS) return;
    const float* y = g_ys1 + (size_t)row*256;
    float s = 0.f;
#pragma unroll
    for (int i = 0; i < 8; i++) s += y[lane + i*32] * __ldg(fcw + lane + i*32);
#pragma unroll
    for (int o = 16; o; o >>= 1) s += __shfl_xor_sync(0xffffffffu, s, o);
    if (lane == 0) out[row] = 1.f/(1.f + __expf(-(s + fcb[0])));
}

// ---------------- launch -----------------------------------------------------
extern "C" void kernel_launch(void* const* d_in, const int* in_sizes, int n_in,
                              void* d_out, int out_size)
{
    const float* x     = (const float*)d_in[0];
    const float* wih0f = (const float*)d_in[1];
    const float* whh0f = (const float*)d_in[2];
    const float* b0f   = (const float*)d_in[3];
    const float* wih0b = (const float*)d_in[4];
    const float* whh0b = (const float*)d_in[5];
    const float* b0b   = (const float*)d_in[6];
    const float* wih1f = (const float*)d_in[7];
    const float* whh1f = (const float*)d_in[8];
    const float* b1f   = (const float*)d_in[9];
    const float* wih1b = (const float*)d_in[10];
    const float* whh1b = (const float*)d_in[11];
    const float* b1b   = (const float*)d_in[12];
    const float* fcw   = (const float*)d_in[13];
    const float* fcb   = (const float*)d_in[14];
    float* out = (float*)d_out;

    cudaFuncSetAttribute(recur_kernel<0>, cudaFuncAttributeMaxDynamicSharedMemorySize, RSMEM);
    cudaFuncSetAttribute(recur_kernel<1>, cudaFuncAttributeMaxDynamicSharedMemorySize, RSMEM);

    dim3 ggrid(8, NROWS/128);
    mma_gemm<DIM, 0><<<ggrid, 256>>>(x, wih0f, wih0b, b0f, b0b);
    recur_kernel<0><<<128, 512, RSMEM>>>(whh0f, whh0b);

    mma_gemm<256, 1><<<ggrid, 256>>>(nullptr, wih1f, wih1b, b1f, b1b);
    recur_kernel<1><<<128, 512, RSMEM>>>(whh1f, whh1b);

    fc_kernel<<<(NROWS*32)/256, 256>>>(fcw, fcb, out);
}

// round 8
// speedup vs baseline: 1.1055x; 1.1055x over previous
#include <cuda_runtime.h>
#include <cstdint>

#define SEQ   4096
#define BATCH 64
#define DIM   96
#define HID   128
#define NROWS (SEQ*BATCH)

using u64 = unsigned long long;

// ---------------- scratch (static device globals) ---------------------------
__device__ float g_zx0[(size_t)NROWS*1024 + 65536];  // [row=t*64+b][n], +1 step pad
__device__ float g_zx1[(size_t)NROWS*1024 + 65536];
__device__ float g_ys0[(size_t)NROWS*256];           // [t][b][2H]
__device__ float g_ys1[(size_t)NROWS*256];

// ---------------- helpers ----------------------------------------------------
__device__ __forceinline__ float sigm(float x)   { return 1.f/(1.f+__expf(-x)); }
__device__ __forceinline__ float tanh_s(float x) { float e=__expf(2.f*x); return 1.f-2.f/(e+1.f); }
__device__ __forceinline__ void ffma2(u64 &d, u64 a, u64 b) {
    asm volatile("fma.rn.f32x2 %0, %1, %2, %0;" : "+l"(d) : "l"(a), "l"(b));
}
__device__ __forceinline__ void lds2(u64 &a, u64 &b, uint32_t addr) {
    asm volatile("ld.shared.v2.u64 {%0,%1}, [%2];" : "=l"(a), "=l"(b) : "r"(addr));
}
__device__ __forceinline__ u64 lds1(uint32_t addr) {
    u64 a; asm volatile("ld.shared.u64 %0, [%1];" : "=l"(a) : "r"(addr)); return a;
}
__device__ __forceinline__ void unpk(float &lo, float &hi, u64 v) {
    asm volatile("mov.b64 {%0,%1}, %2;" : "=f"(lo), "=f"(hi) : "l"(v));
}
__device__ __forceinline__ uint32_t f2tf32(float x) {
    uint32_t r; asm("cvt.rna.tf32.f32 %0, %1;" : "=r"(r) : "f"(x)); return r;
}
__device__ __forceinline__ void mma_tf32(float4 &c,
    uint32_t a0, uint32_t a1, uint32_t a2, uint32_t a3,
    uint32_t b0, uint32_t b1)
{
    asm volatile("mma.sync.aligned.m16n8k8.row.col.f32.tf32.tf32.f32 "
        "{%0,%1,%2,%3}, {%4,%5,%6,%7}, {%8,%9}, {%0,%1,%2,%3};"
        : "+f"(c.x), "+f"(c.y), "+f"(c.z), "+f"(c.w)
        : "r"(a0), "r"(a1), "r"(a2), "r"(a3), "r"(b0), "r"(b1));
}

// ---------------- input-projection GEMM: round-5 proven version --------------
template<int K, int LAYER>
__global__ void __launch_bounds__(256) mma_gemm(
    const float* __restrict__ Aext,
    const float* __restrict__ Wf, const float* __restrict__ Wb,
    const float* __restrict__ bf, const float* __restrict__ bb)
{
    __shared__ uint32_t As[128][36];
    __shared__ uint32_t Ws[128][36];

    const float* A = (LAYER == 0) ? Aext : (const float*)g_ys0;
    float*       Z = LAYER ? g_zx1 : g_zx0;

    const int n0 = blockIdx.x * 128;
    const int m0 = blockIdx.y * 128;
    const float* W    = (n0 < 512) ? (Wf + (size_t)n0*K) : (Wb + (size_t)(n0-512)*K);
    const float* bias = (n0 < 512) ? (bf + n0) : (bb + (n0-512));

    const int tid  = threadIdx.x;
    const int wid  = tid >> 5, lane = tid & 31;
    const int wm   = wid & 3,  wn   = wid >> 2;
    const int g    = lane >> 2, t   = lane & 3;

    float4 acc[2][8];
#pragma unroll
    for (int mi = 0; mi < 2; mi++)
#pragma unroll
        for (int ni = 0; ni < 8; ni++) acc[mi][ni] = make_float4(0.f,0.f,0.f,0.f);

    for (int k0 = 0; k0 < K; k0 += 32) {
#pragma unroll
        for (int i = 0; i < 4; i++) {
            int q = tid + i*256;
            int r = q >> 3, kq = q & 7;
            float4 av = *(const float4*)(A + (size_t)(m0+r)*K + k0 + kq*4);
            uint4 ua = { f2tf32(av.x), f2tf32(av.y), f2tf32(av.z), f2tf32(av.w) };
            *(uint4*)&As[r][kq*4] = ua;
            float4 wv = *(const float4*)(W + (size_t)r*K + k0 + kq*4);
            uint4 uw = { f2tf32(wv.x), f2tf32(wv.y), f2tf32(wv.z), f2tf32(wv.w) };
            *(uint4*)&Ws[r][kq*4] = uw;
        }
        __syncthreads();
#pragma unroll
        for (int kb = 0; kb < 32; kb += 8) {
            uint32_t a[2][4];
#pragma unroll
            for (int mi = 0; mi < 2; mi++) {
                int R = wm*32 + mi*16;
                a[mi][0] = As[R + g    ][kb + t    ];
                a[mi][1] = As[R + g + 8][kb + t    ];
                a[mi][2] = As[R + g    ][kb + t + 4];
                a[mi][3] = As[R + g + 8][kb + t + 4];
            }
#pragma unroll
            for (int ni = 0; ni < 8; ni++) {
                int N8 = wn*64 + ni*8;
                uint32_t b0 = Ws[N8 + g][kb + t    ];
                uint32_t b1 = Ws[N8 + g][kb + t + 4];
                mma_tf32(acc[0][ni], a[0][0], a[0][1], a[0][2], a[0][3], b0, b1);
                mma_tf32(acc[1][ni], a[1][0], a[1][1], a[1][2], a[1][3], b0, b1);
            }
        }
        __syncthreads();
    }

#pragma unroll
    for (int ni = 0; ni < 8; ni++) {
        int ncl = wn*64 + ni*8 + 2*t;
        float2 bv = *(const float2*)(bias + ncl);
#pragma unroll
        for (int mi = 0; mi < 2; mi++) {
            float4 cf = acc[mi][ni];
            int r0 = m0 + wm*32 + mi*16 + g;
            float2 o0 = { cf.x + bv.x, cf.y + bv.y };
            float2 o1 = { cf.z + bv.x, cf.w + bv.y };
            *(float2*)(Z + (size_t)r0*1024 + n0 + ncl)     = o0;
            *(float2*)(Z + (size_t)(r0+8)*1024 + n0 + ncl) = o1;
        }
    }
}

// ---------------- recurrence: one CTA per (cell, batch-PAIR) -----------------
// 64 CTAs x 512 threads. Thread j owns Whh row j (gate=j>>7, unit=j&127) and
// accumulates BOTH batches of the pair per step (weights amortized, 2x ILP).
// Weights: k[0,96) in 48 reg pairs, k[96,128) in smem [16 kp][512 j] (R4 map).
// hs0/hs1: per-batch h[128]. zs: [2 batches][gate*128+unit] (conflict-free).
#define RSMEM (65536 + 1024 + 4096)

template<int LAYER>
__global__ void __launch_bounds__(512, 1) recur_kernel(
    const float* __restrict__ whhf, const float* __restrict__ whhb)
{
    extern __shared__ char smraw[];
    u64*   wsm = (u64*)smraw;                       // [16 kp][512 j]
    float* hs0 = (float*)(smraw + 65536);           // [128]
    float* hs1 = hs0 + 128;                         // [128]
    float* zs  = (float*)(smraw + 65536 + 1024);    // [2][512]

    const int tid  = threadIdx.x;                   // = j (Whh row)
    const int cell = blockIdx.x >> 5;
    const int b0   = (blockIdx.x & 31) * 2;
    const float* whh = cell ? whhb : whhf;
    const float* zx  = LAYER ? g_zx1 : g_zx0;
    float*       ys  = LAYER ? g_ys1 : g_ys0;

    const u64* wrow = (const u64*)whh + (size_t)tid*64;
    u64 wreg[48];
#pragma unroll
    for (int q = 0; q < 48; q++) wreg[q] = __ldg(wrow + q);
#pragma unroll
    for (int q = 0; q < 16; q++) wsm[q*512 + tid] = __ldg(wrow + 48 + q);

    if (tid < 256) { hs0[tid & 127] = 0.f; }        // covers hs0+hs1 (256 floats)

    uint32_t hs0_s = (uint32_t)__cvta_generic_to_shared(hs0);
    uint32_t hs1_s = hs0_s + 512;
    uint32_t wsm_s = (uint32_t)__cvta_generic_to_shared(wsm);

    const float* zptr0 = zx + (size_t)b0*1024 + cell*512 + tid;
    const float* zptr1 = zptr0 + 1024;
    float zc0 = __ldcs(zptr0);
    float zc1 = __ldcs(zptr1);

    // epilogue identity: threads 0..255 -> (be = tid>>7, u = tid&127)
    const int be = tid >> 7;
    const int ue = tid & 127;
    float* ysp = ys + (size_t)(b0 + be)*256 + cell*128 + ue;
    float c = 0.f;

    __syncthreads();

    for (int t = 0; t < SEQ; t++) {
        float zn0 = __ldcs(zptr0 + (size_t)(t+1)*65536);
        float zn1 = __ldcs(zptr1 + (size_t)(t+1)*65536);

        u64 a00 = 0ull, a01 = 0ull, a10 = 0ull, a11 = 0ull;
#pragma unroll
        for (int q = 0; q < 48; q += 2) {                   // k in [0,96)
            u64 ha, hb, hc, hd;
            lds2(ha, hb, hs0_s + q*8);
            lds2(hc, hd, hs1_s + q*8);
            ffma2(a00, wreg[q],   ha);
            ffma2(a01, wreg[q+1], hb);
            ffma2(a10, wreg[q],   hc);
            ffma2(a11, wreg[q+1], hd);
        }
#pragma unroll
        for (int kp = 0; kp < 16; kp += 2) {                // k in [96,128)
            u64 ha, hb, hc, hd;
            lds2(ha, hb, hs0_s + 384 + kp*8);
            lds2(hc, hd, hs1_s + 384 + kp*8);
            u64 wa = lds1(wsm_s + (kp*512     + tid)*8);
            u64 wb = lds1(wsm_s + ((kp+1)*512 + tid)*8);
            ffma2(a00, wa, ha);
            ffma2(a01, wb, hb);
            ffma2(a10, wa, hc);
            ffma2(a11, wb, hd);
        }
        float x0,x1,x2,x3;
        unpk(x0,x1,a00); unpk(x2,x3,a01);
        zs[tid]       = ((x0+x1)+(x2+x3)) + zc0;
        unpk(x0,x1,a10); unpk(x2,x3,a11);
        zs[512 + tid] = ((x0+x1)+(x2+x3)) + zc1;
        zc0 = zn0; zc1 = zn1;
        __syncthreads();

        if (tid < 256) {
            const float* zb = zs + be*512;
            float zi = zb[ue], zf = zb[128+ue], zg = zb[256+ue], zo = zb[384+ue];
            float ig = sigm(zi), fg = sigm(zf), gg = tanh_s(zg), og = sigm(zo);
            c = fg*c + ig*gg;
            float h = og * tanh_s(c);
            (be ? hs1 : hs0)[ue] = h;
            ysp[(size_t)t*16384] = h;
        }
        __syncthreads();
    }
}

// ---------------- final FC + sigmoid ----------------------------------------
__global__ void __launch_bounds__(256) fc_kernel(
    const float* __restrict__ fcw, const float* __restrict__ fcb,
    float* __restrict__ out)
{
    int gtid = blockIdx.x*blockDim.x + threadIdx.x;
    int row = gtid >> 5, lane = gtid & 31;
    if (row >= NROWS) return;
    const float* y = g_ys1 + (size_t)row*256;
    float s = 0.f;
#pragma unroll
    for (int i = 0; i < 8; i++) s += y[lane + i*32] * __ldg(fcw + lane + i*32);
#pragma unroll
    for (int o = 16; o; o >>= 1) s += __shfl_xor_sync(0xffffffffu, s, o);
    if (lane == 0) out[row] = 1.f/(1.f + __expf(-(s + fcb[0])));
}

// ---------------- launch -----------------------------------------------------
extern "C" void kernel_launch(void* const* d_in, const int* in_sizes, int n_in,
                              void* d_out, int out_size)
{
    const float* x     = (const float*)d_in[0];
    const float* wih0f = (const float*)d_in[1];
    const float* whh0f = (const float*)d_in[2];
    const float* b0f   = (const float*)d_in[3];
    const float* wih0b = (const float*)d_in[4];
    const float* whh0b = (const float*)d_in[5];
    const float* b0b   = (const float*)d_in[6];
    const float* wih1f = (const float*)d_in[7];
    const float* whh1f = (const float*)d_in[8];
    const float* b1f   = (const float*)d_in[9];
    const float* wih1b = (const float*)d_in[10];
    const float* whh1b = (const float*)d_in[11];
    const float* b1b   = (const float*)d_in[12];
    const float* fcw   = (const float*)d_in[13];
    const float* fcb   = (const float*)d_in[14];
    float* out = (float*)d_out;

    cudaFuncSetAttribute(recur_kernel<0>, cudaFuncAttributeMaxDynamicSharedMemorySize, RSMEM);
    cudaFuncSetAttribute(recur_kernel<1>, cudaFuncAttributeMaxDynamicSharedMemorySize, RSMEM);

    dim3 ggrid(8, NROWS/128);
    mma_gemm<DIM, 0><<<ggrid, 256>>>(x, wih0f, wih0b, b0f, b0b);
    recur_kernel<0><<<64, 512, RSMEM>>>(whh0f, whh0b);

    mma_gemm<256, 1><<<ggrid, 256>>>(nullptr, wih1f, wih1b, b1f, b1b);
    recur_kernel<1><<<64, 512, RSMEM>>>(whh1f, whh1b);

    fc_kernel<<<(NROWS*32)/256, 256>>>(fcw, fcb, out);
}